// round 10
// baseline (speedup 1.0000x reference)
#include <cuda_runtime.h>

#define DIMX 200
#define DIMY 200
#define DIMZ 16
#define NDIMS 16
#define KWIN 6
#define VOXEL 0.4f
#define VMINX -40.0f
#define VMINY -40.0f
#define VMINZ -1.0f

// Tiles: 4 x 4 x 16 voxels = 256 voxels = 256 threads/block
#define TX 4
#define TY 4
#define NTX (DIMX / TX)          // 50
#define NTY (DIMY / TY)          // 50
#define NTILES (NTX * NTY)       // 2500
#define CAP 256                  // ids per bin (expected ~34, Poisson-safe)
#define CHUNK 64                 // gaussians staged in smem per iteration
#define NMAX 65536
#define GBLOCKS 500              // persistent gather blocks: 5 tiles each, all resident

// Scratch (static device globals, zero-initialized at load; gather resets
// counters after use so every launch sees zeros — no separate memset kernel)
__device__ int   g_cnt[NTILES];
__device__ int   g_ids[NTILES * CAP];
__device__ float g_prec[NMAX * 12];  // mx,my,mz,i00 | i01,i02,i11,i12 | i22,op,startP,endP

// ---------------------------------------------------------------------------
// Kernel 1: per-gaussian precompute (icov, bbox) + scatter id into tile bins
// ---------------------------------------------------------------------------
__global__ void k_bin(const float* __restrict__ means,
                      const float* __restrict__ covs,
                      const float* __restrict__ opac,
                      int n) {
    int g = blockIdx.x * blockDim.x + threadIdx.x;
    if (g >= n) return;

    const float* c = covs + g * 9;
    float a00 = c[0], a01 = c[1], a02 = c[2];
    float a11 = c[4], a12 = c[5], a22 = c[8];
    float c00 = a11 * a22 - a12 * a12;
    float c01 = a02 * a12 - a01 * a22;
    float c02 = a01 * a12 - a02 * a11;
    float det = a00 * c00 + a01 * c01 + a02 * c02;
    float inv = 1.0f / det;
    float i00 = c00 * inv;
    float i01 = c01 * inv;
    float i02 = c02 * inv;
    float i11 = (a00 * a22 - a02 * a02) * inv;
    float i12 = (a01 * a02 - a00 * a12) * inv;
    float i22 = (a00 * a11 - a01 * a01) * inv;

    float mx = means[g * 3 + 0];
    float my = means[g * 3 + 1];
    float mz = means[g * 3 + 2];
    float rx = 3.0f * sqrtf(a00);
    float ry = 3.0f * sqrtf(a11);
    float rz = 3.0f * sqrtf(a22);

    // trunc-toward-zero matches reference (coords positive after shift)
    int sx = max(0, (int)((mx - rx - VMINX) / VOXEL));
    int sy = max(0, (int)((my - ry - VMINY) / VOXEL));
    int sz = max(0, (int)((mz - rz - VMINZ) / VOXEL));
    int ex = min(DIMX, (int)((mx + rx - VMINX) / VOXEL) + 1);
    int ey = min(DIMY, (int)((my + ry - VMINY) / VOXEL) + 1);
    int ez = min(DIMZ, (int)((mz + rz - VMINZ) / VOXEL) + 1);
    // reference only visits offs in [0, K)
    ex = min(ex, sx + KWIN);
    ey = min(ey, sy + KWIN);
    ez = min(ez, sz + KWIN);

    int sP = sx | (sy << 8) | (sz << 16);
    int eP = ex | (ey << 8) | (ez << 16);

    float4* p = (float4*)(g_prec + (size_t)g * 12);
    p[0] = make_float4(mx, my, mz, i00);
    p[1] = make_float4(i01, i02, i11, i12);
    p[2] = make_float4(i22, opac[g], __int_as_float(sP), __int_as_float(eP));

    if (sx >= ex || sy >= ey || sz >= ez) return;

    int tx0 = sx / TX, tx1 = (ex - 1) / TX;
    int ty0 = sy / TY, ty1 = (ey - 1) / TY;
    for (int tx = tx0; tx <= tx1; tx++)
        for (int ty = ty0; ty <= ty1; ty++) {
            int t = tx * NTY + ty;
            int slot = atomicAdd(&g_cnt[t], 1);
            if (slot < CAP) g_ids[t * CAP + slot] = g;
        }
}

// ---------------------------------------------------------------------------
// Kernel 2: gather. Persistent: GBLOCKS blocks, each handles NTILES/GBLOCKS
// tiles (strided -> spatially decorrelated load). One thread per voxel of the
// current 4x4x16 tile. Warp layout: lane = lx | (ly<<2) | (dz<<4); warp w
// owns z in {2w, 2w+1}. Lanes cull gaussians in parallel against the warp's
// z-slab, ballot-compact survivors, evaluate densely. Register accumulation,
// inline normalize, single write. No output atomics, no init/normalize pass.
// ---------------------------------------------------------------------------
__global__ __launch_bounds__(256) void k_gather(const float4* __restrict__ feat4,
                                                float* __restrict__ gdens,
                                                float* __restrict__ gfeat) {
    __shared__ float4 s_prec[CHUNK * 3];
    __shared__ float4 s_feat[CHUNK * 4];
    __shared__ short  s_wl[8][CHUNK];   // per-warp compacted survivor indices

    const int t = threadIdx.x;
    const int lane = t & 31;
    const int w = t >> 5;             // warp id = z slab
    const int lx = lane & 3;
    const int ly = (lane >> 2) & 3;
    const int iz = 2 * w + (lane >> 4);
    const int zb = 2 * w;             // warp-uniform z base
    const float pzc = (float)iz * VOXEL + VMINZ;

    const float4* prec4 = (const float4*)g_prec;

    for (int b = blockIdx.x; b < NTILES; b += GBLOCKS) {
        const int ty = b % NTY;
        const int tx = b / NTY;
        const int ix = tx * TX + lx;
        const int iy = ty * TY + ly;
        const float px = (float)ix * VOXEL + VMINX;
        const float py = (float)iy * VOXEL + VMINY;

        const int n = min(g_cnt[b], CAP);
        const int* __restrict__ bin = g_ids + b * CAP;

        float accd = 0.0f;
        float f0x = 0, f0y = 0, f0z = 0, f0w = 0;
        float f1x = 0, f1y = 0, f1z = 0, f1w = 0;
        float f2x = 0, f2y = 0, f2z = 0, f2w = 0;
        float f3x = 0, f3y = 0, f3z = 0, f3w = 0;

        for (int base = 0; base < n; base += CHUNK) {
            const int m = min(CHUNK, n - base);

            // stage records + features; ids read straight from gmem (L1 hits)
            for (int i = t; i < m * 3; i += 256) {
                int j = i / 3;
                s_prec[i] = prec4[(size_t)__ldg(bin + base + j) * 3 + (i - j * 3)];
            }
            for (int i = t; i < m * 4; i += 256) {
                s_feat[i] = feat4[(size_t)__ldg(bin + base + (i >> 2)) * 4 + (i & 3)];
            }
            __syncthreads();

            // ---- lane-parallel z-cull + ballot compaction into s_wl[w] ----
            int mc = 0;
            for (int i0 = 0; i0 < m; i0 += 32) {
                int i = i0 + lane;
                bool zpass = false;
                if (i < m) {
                    float4 p2 = s_prec[i * 3 + 2];
                    int zlo = __float_as_int(p2.z) >> 16;
                    int zhi = __float_as_int(p2.w) >> 16;
                    zpass = (zhi > zb) && (zlo < zb + 2);
                }
                unsigned bal = __ballot_sync(0xFFFFFFFFu, zpass);
                if (zpass) {
                    int pos = mc + __popc(bal & ((1u << lane) - 1u));
                    s_wl[w][pos] = (short)i;
                }
                mc += __popc(bal);
            }
            __syncwarp();

            // ---- dense eval over survivors ----
            for (int k = 0; k < mc; k++) {
                int j = s_wl[w][k];
                float4 p2 = s_prec[j * 3 + 2];
                int sP = __float_as_int(p2.z);
                int eP = __float_as_int(p2.w);
                bool pass = (ix >= (sP & 255)) & (ix < (eP & 255))
                          & (iy >= ((sP >> 8) & 255)) & (iy < ((eP >> 8) & 255))
                          & (iz >= (sP >> 16)) & (iz < (eP >> 16));
                if (pass) {
                    float4 p0 = s_prec[j * 3 + 0];
                    float4 p1 = s_prec[j * 3 + 1];
                    float dx = px - p0.x;
                    float dy = py - p0.y;
                    float dz = pzc - p0.z;
                    float mahal = p0.w * dx * dx + p1.z * dy * dy + p2.x * dz * dz
                                + 2.0f * (p1.x * dx * dy + p1.y * dx * dz + p1.w * dy * dz);
                    float dens = p2.y * __expf(-0.5f * mahal);
                    accd += dens;
                    float4 q0 = s_feat[j * 4 + 0];
                    float4 q1 = s_feat[j * 4 + 1];
                    float4 q2 = s_feat[j * 4 + 2];
                    float4 q3 = s_feat[j * 4 + 3];
                    f0x += dens * q0.x; f0y += dens * q0.y; f0z += dens * q0.z; f0w += dens * q0.w;
                    f1x += dens * q1.x; f1y += dens * q1.y; f1z += dens * q1.z; f1w += dens * q1.w;
                    f2x += dens * q2.x; f2y += dens * q2.y; f2z += dens * q2.z; f2w += dens * q2.w;
                    f3x += dens * q3.x; f3y += dens * q3.y; f3z += dens * q3.z; f3w += dens * q3.w;
                }
            }
            __syncthreads();
        }

        // reset bin counter for the next launch (keeps the no-memset invariant)
        if (t == 0) g_cnt[b] = 0;

        const int idx = (ix * DIMY + iy) * DIMZ + iz;
        gdens[idx] = accd;

        const float s = 1.0f / fmaxf(accd, 1e-6f);
        f3w += 1e-5f;  // reference seeds channel 15 with 1e-5 before normalize
        float4* fp = (float4*)(gfeat + (size_t)idx * NDIMS);
        fp[0] = make_float4(f0x * s, f0y * s, f0z * s, f0w * s);
        fp[1] = make_float4(f1x * s, f1y * s, f1z * s, f1w * s);
        fp[2] = make_float4(f2x * s, f2y * s, f2z * s, f2w * s);
        fp[3] = make_float4(f3x * s, f3y * s, f3z * s, f3w * s);
    }
}

extern "C" void kernel_launch(void* const* d_in, const int* in_sizes, int n_in,
                              void* d_out, int out_size) {
    const float* means = (const float*)d_in[0];   // [N,3]
    const float* covs  = (const float*)d_in[1];   // [N,3,3]
    const float* opac  = (const float*)d_in[2];   // [N]
    const float* feats = (const float*)d_in[3];   // [N,16]
    const int n_gauss = in_sizes[2];

    float* gdens = (float*)d_out;                                  // [200*200*16]
    float* gfeat = gdens + (size_t)DIMX * DIMY * DIMZ;             // [...,16]

    k_bin<<<(n_gauss + 255) / 256, 256>>>(means, covs, opac, n_gauss);
    k_gather<<<GBLOCKS, 256>>>((const float4*)feats, gdens, gfeat);
}

// round 12
// speedup vs baseline: 1.1721x; 1.1721x over previous
#include <cuda_runtime.h>

#define DIMX 200
#define DIMY 200
#define DIMZ 16
#define NDIMS 16
#define KWIN 6
#define VOXEL 0.4f
#define VMINX -40.0f
#define VMINY -40.0f
#define VMINZ -1.0f

// Tiles: 4 x 4 x 16 voxels = 256 voxels = 256 threads/block
#define TX 4
#define TY 4
#define NTX (DIMX / TX)          // 50
#define NTY (DIMY / TY)          // 50
#define NTILES (NTX * NTY)       // 2500
#define CAP 256                  // ids per bin (expected ~34, Poisson-safe)
#define CHUNK 64                 // gaussians staged in smem per iteration
#define NMAX 65536

// Scratch (static device globals, zero-initialized at load; gather resets
// counters after use so every launch sees zeros — no separate memset kernel)
__device__ int   g_cnt[NTILES];
__device__ int   g_ids[NTILES * CAP];
__device__ float g_prec[NMAX * 12];  // mx,my,mz,i00 | i01,i02,i11,i12 | i22,op,startP,endP

// ---------------------------------------------------------------------------
// Kernel 1: per-gaussian precompute (icov, bbox) + scatter id into tile bins
// ---------------------------------------------------------------------------
__global__ void k_bin(const float* __restrict__ means,
                      const float* __restrict__ covs,
                      const float* __restrict__ opac,
                      int n) {
    int g = blockIdx.x * blockDim.x + threadIdx.x;
    if (g >= n) return;

    const float* c = covs + g * 9;
    float a00 = c[0], a01 = c[1], a02 = c[2];
    float a11 = c[4], a12 = c[5], a22 = c[8];
    float c00 = a11 * a22 - a12 * a12;
    float c01 = a02 * a12 - a01 * a22;
    float c02 = a01 * a12 - a02 * a11;
    float det = a00 * c00 + a01 * c01 + a02 * c02;
    float inv = 1.0f / det;
    float i00 = c00 * inv;
    float i01 = c01 * inv;
    float i02 = c02 * inv;
    float i11 = (a00 * a22 - a02 * a02) * inv;
    float i12 = (a01 * a02 - a00 * a12) * inv;
    float i22 = (a00 * a11 - a01 * a01) * inv;

    float mx = means[g * 3 + 0];
    float my = means[g * 3 + 1];
    float mz = means[g * 3 + 2];
    float rx = 3.0f * sqrtf(a00);
    float ry = 3.0f * sqrtf(a11);
    float rz = 3.0f * sqrtf(a22);

    // trunc-toward-zero matches reference (coords positive after shift)
    int sx = max(0, (int)((mx - rx - VMINX) / VOXEL));
    int sy = max(0, (int)((my - ry - VMINY) / VOXEL));
    int sz = max(0, (int)((mz - rz - VMINZ) / VOXEL));
    int ex = min(DIMX, (int)((mx + rx - VMINX) / VOXEL) + 1);
    int ey = min(DIMY, (int)((my + ry - VMINY) / VOXEL) + 1);
    int ez = min(DIMZ, (int)((mz + rz - VMINZ) / VOXEL) + 1);
    // reference only visits offs in [0, K)
    ex = min(ex, sx + KWIN);
    ey = min(ey, sy + KWIN);
    ez = min(ez, sz + KWIN);

    int sP = sx | (sy << 8) | (sz << 16);
    int eP = ex | (ey << 8) | (ez << 16);

    float4* p = (float4*)(g_prec + (size_t)g * 12);
    p[0] = make_float4(mx, my, mz, i00);
    p[1] = make_float4(i01, i02, i11, i12);
    p[2] = make_float4(i22, opac[g], __int_as_float(sP), __int_as_float(eP));

    if (sx >= ex || sy >= ey || sz >= ez) return;

    int tx0 = sx / TX, tx1 = (ex - 1) / TX;
    int ty0 = sy / TY, ty1 = (ey - 1) / TY;
    for (int tx = tx0; tx <= tx1; tx++)
        for (int ty = ty0; ty <= ty1; ty++) {
            int t = tx * NTY + ty;
            int slot = atomicAdd(&g_cnt[t], 1);
            if (slot < CAP) g_ids[t * CAP + slot] = g;
        }
}

// ---------------------------------------------------------------------------
// Kernel 2: gather. One block per 4x4x16 tile, one thread per voxel.
// Warp layout: lane = lx | (ly<<2) | (dz<<4); warp w owns z in {2w, 2w+1}.
// Per chunk: lanes cull gaussians in parallel against the warp's z-slab,
// ballot-compact survivors into a per-warp worklist, then evaluate densely.
// __launch_bounds__(256, 5): cap regs at 48 so 5 blocks fit per SM (62.5% occ)
// — R9/R10 showed issue% tracks occupancy ~1:1 in this kernel.
// ---------------------------------------------------------------------------
__global__ __launch_bounds__(256, 5) void k_gather(const float4* __restrict__ feat4,
                                                   float* __restrict__ gdens,
                                                   float* __restrict__ gfeat) {
    __shared__ float4 s_prec[CHUNK * 3];
    __shared__ float4 s_feat[CHUNK * 4];
    __shared__ short  s_wl[8][CHUNK];   // per-warp compacted survivor indices

    const int b = blockIdx.x;
    const int ty = b % NTY;
    const int tx = b / NTY;
    const int t = threadIdx.x;

    const int lane = t & 31;
    const int w = t >> 5;             // warp id = z slab
    const int lx = lane & 3;
    const int ly = (lane >> 2) & 3;
    const int iz = 2 * w + (lane >> 4);
    const int zb = 2 * w;             // warp-uniform z base
    const int ix = tx * TX + lx;
    const int iy = ty * TY + ly;

    const float px = (float)ix * VOXEL + VMINX;
    const float py = (float)iy * VOXEL + VMINY;
    const float pz = (float)iz * VOXEL + VMINZ;

    const int n = min(g_cnt[b], CAP);
    const int* __restrict__ bin = g_ids + b * CAP;

    float accd = 0.0f;
    float f0x = 0, f0y = 0, f0z = 0, f0w = 0;
    float f1x = 0, f1y = 0, f1z = 0, f1w = 0;
    float f2x = 0, f2y = 0, f2z = 0, f2w = 0;
    float f3x = 0, f3y = 0, f3z = 0, f3w = 0;

    const float4* prec4 = (const float4*)g_prec;

    for (int base = 0; base < n; base += CHUNK) {
        const int m = min(CHUNK, n - base);

        // stage records + features; ids read straight from gmem (L1 broadcast)
        for (int i = t; i < m * 3; i += 256) {
            int j = i / 3;
            s_prec[i] = prec4[(size_t)__ldg(bin + base + j) * 3 + (i - j * 3)];
        }
        for (int i = t; i < m * 4; i += 256) {
            s_feat[i] = feat4[(size_t)__ldg(bin + base + (i >> 2)) * 4 + (i & 3)];
        }
        __syncthreads();

        // ---- lane-parallel z-cull + ballot compaction into s_wl[w] ----
        int mc = 0;
        for (int i0 = 0; i0 < m; i0 += 32) {
            int i = i0 + lane;
            bool zpass = false;
            if (i < m) {
                float4 p2 = s_prec[i * 3 + 2];
                int zlo = __float_as_int(p2.z) >> 16;
                int zhi = __float_as_int(p2.w) >> 16;
                zpass = (zhi > zb) && (zlo < zb + 2);
            }
            unsigned bal = __ballot_sync(0xFFFFFFFFu, zpass);
            if (zpass) {
                int pos = mc + __popc(bal & ((1u << lane) - 1u));
                s_wl[w][pos] = (short)i;
            }
            mc += __popc(bal);
        }
        __syncwarp();

        // ---- dense eval over survivors ----
#pragma unroll 2
        for (int k = 0; k < mc; k++) {
            int j = s_wl[w][k];
            float4 p2 = s_prec[j * 3 + 2];
            int sP = __float_as_int(p2.z);
            int eP = __float_as_int(p2.w);
            bool pass = (ix >= (sP & 255)) & (ix < (eP & 255))
                      & (iy >= ((sP >> 8) & 255)) & (iy < ((eP >> 8) & 255))
                      & (iz >= (sP >> 16)) & (iz < (eP >> 16));
            if (pass) {
                float4 p0 = s_prec[j * 3 + 0];
                float4 p1 = s_prec[j * 3 + 1];
                float dx = px - p0.x;
                float dy = py - p0.y;
                float dz = pz - p0.z;
                float mahal = p0.w * dx * dx + p1.z * dy * dy + p2.x * dz * dz
                            + 2.0f * (p1.x * dx * dy + p1.y * dx * dz + p1.w * dy * dz);
                float dens = p2.y * __expf(-0.5f * mahal);
                accd += dens;
                float4 q0 = s_feat[j * 4 + 0];
                float4 q1 = s_feat[j * 4 + 1];
                float4 q2 = s_feat[j * 4 + 2];
                float4 q3 = s_feat[j * 4 + 3];
                f0x += dens * q0.x; f0y += dens * q0.y; f0z += dens * q0.z; f0w += dens * q0.w;
                f1x += dens * q1.x; f1y += dens * q1.y; f1z += dens * q1.z; f1w += dens * q1.w;
                f2x += dens * q2.x; f2y += dens * q2.y; f2z += dens * q2.z; f2w += dens * q2.w;
                f3x += dens * q3.x; f3y += dens * q3.y; f3z += dens * q3.z; f3w += dens * q3.w;
            }
        }
        __syncthreads();
    }

    // reset bin counter for the next launch (keeps the no-memset invariant)
    if (t == 0) g_cnt[b] = 0;

    const int idx = (ix * DIMY + iy) * DIMZ + iz;
    gdens[idx] = accd;

    const float s = 1.0f / fmaxf(accd, 1e-6f);
    f3w += 1e-5f;  // reference seeds channel 15 with 1e-5 before normalize
    float4* fp = (float4*)(gfeat + (size_t)idx * NDIMS);
    fp[0] = make_float4(f0x * s, f0y * s, f0z * s, f0w * s);
    fp[1] = make_float4(f1x * s, f1y * s, f1z * s, f1w * s);
    fp[2] = make_float4(f2x * s, f2y * s, f2z * s, f2w * s);
    fp[3] = make_float4(f3x * s, f3y * s, f3z * s, f3w * s);
}

extern "C" void kernel_launch(void* const* d_in, const int* in_sizes, int n_in,
                              void* d_out, int out_size) {
    const float* means = (const float*)d_in[0];   // [N,3]
    const float* covs  = (const float*)d_in[1];   // [N,3,3]
    const float* opac  = (const float*)d_in[2];   // [N]
    const float* feats = (const float*)d_in[3];   // [N,16]
    const int n_gauss = in_sizes[2];

    float* gdens = (float*)d_out;                                  // [200*200*16]
    float* gfeat = gdens + (size_t)DIMX * DIMY * DIMZ;             // [...,16]

    k_bin<<<(n_gauss + 255) / 256, 256>>>(means, covs, opac, n_gauss);
    k_gather<<<NTILES, 256>>>((const float4*)feats, gdens, gfeat);
}

// round 14
// speedup vs baseline: 1.2865x; 1.0977x over previous
#include <cuda_runtime.h>

#define DIMX 200
#define DIMY 200
#define DIMZ 16
#define NDIMS 16
#define KWIN 6
#define VOXEL 0.4f
#define VMINX -40.0f
#define VMINY -40.0f
#define VMINZ -1.0f

// Tiles: 4 x 4 x 16 voxels = 256 voxels = 256 threads/block
#define TX 4
#define TY 4
#define NTX (DIMX / TX)          // 50
#define NTY (DIMY / TY)          // 50
#define NTILES (NTX * NTY)       // 2500
#define CAP 256                  // ids per bin (expected ~34, Poisson-safe)
#define CHUNK 64                 // gaussians staged in smem per iteration
#define NMAX 65536

// -0.5 * log2(e): folds the exp(-0.5*mahal) scale into the inverse covariance
#define NEGHALF_LOG2E (-0.72134752044448170368f)

typedef unsigned long long u64;

__device__ __forceinline__ u64 pack2(float x, float y) {
    u64 r; asm("mov.b64 %0, {%1, %2};" : "=l"(r) : "f"(x), "f"(y)); return r;
}
__device__ __forceinline__ void unpack2(u64 v, float& x, float& y) {
    asm("mov.b64 {%0, %1}, %2;" : "=f"(x), "=f"(y) : "l"(v));
}
__device__ __forceinline__ void fma2(u64& a, u64 b, u64 c) {
    asm("fma.rn.f32x2 %0, %1, %2, %0;" : "+l"(a) : "l"(b), "l"(c));
}
__device__ __forceinline__ u64 mul2(u64 a, u64 b) {
    u64 r; asm("mul.rn.f32x2 %0, %1, %2;" : "=l"(r) : "l"(a), "l"(b)); return r;
}
__device__ __forceinline__ u64 add2(u64 a, u64 b) {
    u64 r; asm("add.rn.f32x2 %0, %1, %2;" : "=l"(r) : "l"(a), "l"(b)); return r;
}
__device__ __forceinline__ float ex2(float x) {
    float r; asm("ex2.approx.f32 %0, %1;" : "=f"(r) : "f"(x)); return r;
}

// Scratch (static device globals, zero-initialized at load; gather resets
// counters after use so every launch sees zeros — no separate memset kernel)
__device__ int   g_cnt[NTILES];
__device__ int   g_ids[NTILES * CAP];
// per-gaussian record, 4 x float4:
//  p0 = (mx, my, mz, op)
//  p1 = (s00, t01, t02, s11)   scaled icov: s = NEGHALF_LOG2E*icov, t = 2*s
//  p2 = (t12, s22, xlo, xhi)   bbox edges in world coords (exact-compare safe)
//  p3 = (ylo, yhi, zlo, zhi)
__device__ float g_prec[NMAX * 16];

// ---------------------------------------------------------------------------
// Kernel 1: per-gaussian precompute (icov, bbox) + scatter id into tile bins
// ---------------------------------------------------------------------------
__global__ void k_bin(const float* __restrict__ means,
                      const float* __restrict__ covs,
                      const float* __restrict__ opac,
                      int n) {
    int g = blockIdx.x * blockDim.x + threadIdx.x;
    if (g >= n) return;

    const float* c = covs + g * 9;
    float a00 = c[0], a01 = c[1], a02 = c[2];
    float a11 = c[4], a12 = c[5], a22 = c[8];
    float c00 = a11 * a22 - a12 * a12;
    float c01 = a02 * a12 - a01 * a22;
    float c02 = a01 * a12 - a02 * a11;
    float det = a00 * c00 + a01 * c01 + a02 * c02;
    float inv = NEGHALF_LOG2E / det;       // fold -0.5*log2e into icov
    float s00 = c00 * inv;
    float s01 = c01 * inv;
    float s02 = c02 * inv;
    float s11 = (a00 * a22 - a02 * a02) * inv;
    float s12 = (a01 * a02 - a00 * a12) * inv;
    float s22 = (a00 * a11 - a01 * a01) * inv;

    float mx = means[g * 3 + 0];
    float my = means[g * 3 + 1];
    float mz = means[g * 3 + 2];
    float rx = 3.0f * sqrtf(a00);
    float ry = 3.0f * sqrtf(a11);
    float rz = 3.0f * sqrtf(a22);

    // trunc-toward-zero matches reference (coords positive after shift)
    int sx = max(0, (int)((mx - rx - VMINX) / VOXEL));
    int sy = max(0, (int)((my - ry - VMINY) / VOXEL));
    int sz = max(0, (int)((mz - rz - VMINZ) / VOXEL));
    int ex = min(DIMX, (int)((mx + rx - VMINX) / VOXEL) + 1);
    int ey = min(DIMY, (int)((my + ry - VMINY) / VOXEL) + 1);
    int ez = min(DIMZ, (int)((mz + rz - VMINZ) / VOXEL) + 1);
    // reference only visits offs in [0, K)
    ex = min(ex, sx + KWIN);
    ey = min(ey, sy + KWIN);
    ez = min(ez, sz + KWIN);

    // bbox edges as world-coord floats; identical formula to voxel coords in
    // the gather -> boundary comparisons are bitwise exact
    float xlo = (float)sx * VOXEL + VMINX, xhi = (float)ex * VOXEL + VMINX;
    float ylo = (float)sy * VOXEL + VMINY, yhi = (float)ey * VOXEL + VMINY;
    float zlo = (float)sz * VOXEL + VMINZ, zhi = (float)ez * VOXEL + VMINZ;

    float4* p = (float4*)(g_prec + (size_t)g * 16);
    p[0] = make_float4(mx, my, mz, opac[g]);
    p[1] = make_float4(s00, 2.0f * s01, 2.0f * s02, s11);
    p[2] = make_float4(2.0f * s12, s22, xlo, xhi);
    p[3] = make_float4(ylo, yhi, zlo, zhi);

    if (sx >= ex || sy >= ey || sz >= ez) return;

    int tx0 = sx / TX, tx1 = (ex - 1) / TX;
    int ty0 = sy / TY, ty1 = (ey - 1) / TY;
    for (int tx = tx0; tx <= tx1; tx++)
        for (int ty = ty0; ty <= ty1; ty++) {
            int t = tx * NTY + ty;
            int slot = atomicAdd(&g_cnt[t], 1);
            if (slot < CAP) g_ids[t * CAP + slot] = g;
        }
}

// ---------------------------------------------------------------------------
// Kernel 2: gather. One block per 4x4x16 tile, one thread per voxel.
// Warp layout: lane = lx | (ly<<2) | (dz<<4); warp w owns z in {2w, 2w+1}.
// Lanes cull gaussians in parallel against the warp's z-slab (float-exact),
// ballot-compact survivors, evaluate densely with f32x2 packed accumulation.
// ---------------------------------------------------------------------------
__global__ __launch_bounds__(256, 5) void k_gather(const float4* __restrict__ feat4,
                                                   float* __restrict__ gdens,
                                                   float* __restrict__ gfeat) {
    __shared__ float4 s_prec[CHUNK * 4];
    __shared__ float4 s_feat[CHUNK * 4];
    __shared__ short  s_wl[8][CHUNK];   // per-warp compacted survivor indices

    const int b = blockIdx.x;
    const int ty = b % NTY;
    const int tx = b / NTY;
    const int t = threadIdx.x;

    const int lane = t & 31;
    const int w = t >> 5;             // warp id = z slab
    const int lx = lane & 3;
    const int ly = (lane >> 2) & 3;
    const int iz = 2 * w + (lane >> 4);
    const int ix = tx * TX + lx;
    const int iy = ty * TY + ly;

    const float px = (float)ix * VOXEL + VMINX;
    const float py = (float)iy * VOXEL + VMINY;
    const float pz = (float)iz * VOXEL + VMINZ;
    // warp z-slab voxel coords (exact same formula as zlo/zhi in k_bin)
    const float slabLo = (float)(2 * w) * VOXEL + VMINZ;
    const float slabHi = (float)(2 * w + 1) * VOXEL + VMINZ;

    const int n = min(g_cnt[b], CAP);
    const int* __restrict__ bin = g_ids + b * CAP;

    float accd = 0.0f;
    u64 fa0 = 0, fa1 = 0, fa2 = 0, fa3 = 0, fa4 = 0, fa5 = 0, fa6 = 0, fa7 = 0;

    const float4* prec4 = (const float4*)g_prec;

    for (int base = 0; base < n; base += CHUNK) {
        const int m = min(CHUNK, n - base);

        // stage records + features; ids read straight from gmem (L1 broadcast)
        for (int i = t; i < m * 4; i += 256) {
            s_prec[i] = prec4[(size_t)__ldg(bin + base + (i >> 2)) * 4 + (i & 3)];
        }
        for (int i = t; i < m * 4; i += 256) {
            s_feat[i] = feat4[(size_t)__ldg(bin + base + (i >> 2)) * 4 + (i & 3)];
        }
        __syncthreads();

        // ---- lane-parallel z-cull + ballot compaction into s_wl[w] ----
        int mc = 0;
        for (int i0 = 0; i0 < m; i0 += 32) {
            int i = i0 + lane;
            bool zpass = false;
            if (i < m) {
                float4 p3 = s_prec[i * 4 + 3];
                zpass = (p3.z <= slabHi) && (p3.w > slabLo);
            }
            unsigned bal = __ballot_sync(0xFFFFFFFFu, zpass);
            if (zpass) {
                int pos = mc + __popc(bal & ((1u << lane) - 1u));
                s_wl[w][pos] = (short)i;
            }
            mc += __popc(bal);
        }
        __syncwarp();

        // ---- dense eval over survivors ----
        for (int k = 0; k < mc; k++) {
            int j = s_wl[w][k];
            float4 p2 = s_prec[j * 4 + 2];
            float4 p3 = s_prec[j * 4 + 3];
            bool pass = (px >= p2.z) & (px < p2.w)
                      & (py >= p3.x) & (py < p3.y)
                      & (pz >= p3.z) & (pz < p3.w);
            if (pass) {
                float4 p0 = s_prec[j * 4 + 0];
                float4 p1 = s_prec[j * 4 + 1];
                float dx = px - p0.x;
                float dy = py - p0.y;
                float dz = pz - p0.z;
                // e = -0.5*log2e*mahal (scale prefolded into s/t coefficients)
                float e = dx * (p1.x * dx + p1.y * dy + p1.z * dz)
                        + dy * (p1.w * dy + p2.x * dz)
                        + dz * (p2.y * dz);
                float dens = p0.w * ex2(e);
                accd += dens;
                u64 dd = pack2(dens, dens);
                const ulonglong2* q = (const ulonglong2*)(s_feat + j * 4);
                ulonglong2 q01 = q[0], q23 = q[1], q45 = q[2], q67 = q[3];
                fma2(fa0, dd, q01.x); fma2(fa1, dd, q01.y);
                fma2(fa2, dd, q23.x); fma2(fa3, dd, q23.y);
                fma2(fa4, dd, q45.x); fma2(fa5, dd, q45.y);
                fma2(fa6, dd, q67.x); fma2(fa7, dd, q67.y);
            }
        }
        __syncthreads();
    }

    // reset bin counter for the next launch (keeps the no-memset invariant)
    if (t == 0) g_cnt[b] = 0;

    const int idx = (ix * DIMY + iy) * DIMZ + iz;
    gdens[idx] = accd;

    const float s = 1.0f / fmaxf(accd, 1e-6f);
    const u64 ss = pack2(s, s);
    fa7 = add2(fa7, pack2(0.0f, 1e-5f));  // reference seeds ch15 with 1e-5
    ulonglong2* fp = (ulonglong2*)(gfeat + (size_t)idx * NDIMS);
    fp[0] = make_ulonglong2(mul2(fa0, ss), mul2(fa1, ss));
    fp[1] = make_ulonglong2(mul2(fa2, ss), mul2(fa3, ss));
    fp[2] = make_ulonglong2(mul2(fa4, ss), mul2(fa5, ss));
    fp[3] = make_ulonglong2(mul2(fa6, ss), mul2(fa7, ss));
}

extern "C" void kernel_launch(void* const* d_in, const int* in_sizes, int n_in,
                              void* d_out, int out_size) {
    const float* means = (const float*)d_in[0];   // [N,3]
    const float* covs  = (const float*)d_in[1];   // [N,3,3]
    const float* opac  = (const float*)d_in[2];   // [N]
    const float* feats = (const float*)d_in[3];   // [N,16]
    const int n_gauss = in_sizes[2];

    float* gdens = (float*)d_out;                                  // [200*200*16]
    float* gfeat = gdens + (size_t)DIMX * DIMY * DIMZ;             // [...,16]

    k_bin<<<(n_gauss + 255) / 256, 256>>>(means, covs, opac, n_gauss);
    k_gather<<<NTILES, 256>>>((const float4*)feats, gdens, gfeat);
}